// round 11
// baseline (speedup 1.0000x reference)
#include <cuda_runtime.h>
#include <math.h>

#define BB 16
#define TT 750
#define FF 4096
#define CC 20
#define KTOP 93
#define ROWS (BB*TT)

// ---- output layout (flattened tuple, reference return order) ----
#define OFF_SACT 0
#define OFF_SBKG (BB*CC)
#define OFF_FACT (2*BB*CC)
#define OFF_FBKG (OFF_FACT + BB*KTOP*FF)
#define OFF_FEAT (OFF_FBKG + BB*KTOP*FF)
#define OFF_CSM  (OFF_FEAT + ROWS*FF)

// ---- scratch ----
__device__ float g_cas[ROWS*CC];
__device__ float g_mag[ROWS];
__device__ int   g_idx_act[BB*KTOP];
__device__ int   g_idx_bkg[BB*KTOP];
__device__ float g_actmean[BB*CC];

// ============================================================
// K1: fused  cas = (x*mask)@W^T,  mag = ||x||,  features copy,
//            cas_softmax epilogue.
// 256 thr = 32 rows x 8 f-lanes, 1 row/thread (low reg footprint),
// 3 blocks/SM forced -> 24 warps/SM, single wave (375 blocks).
// Per chunk: all 8 x/m LDG.128 front-batched; W double-buffered
// in smem with 10-reg prefetch.
// ============================================================
constexpr int TPB1 = 256;
constexpr int TM   = 32;           // rows per block
constexpr int CF   = 128;          // F-chunk floats
constexpr int NCH  = FF/CF;        // 32 chunks
constexpr int WPT  = CC*CF/TPB1;   // 10 W floats staged per thread

__global__ __launch_bounds__(TPB1, 3) void k1_main(
    const float* __restrict__ x, const float* __restrict__ W,
    const float* __restrict__ m, float* __restrict__ out)
{
    __shared__ float sW[2][CC*CF];         // 2 x 10 KB
    const int tid = threadIdx.x;
    const int j = tid & 7;                  // f-lane
    const int row = blockIdx.x * TM + (tid >> 3);

    const float4* __restrict__ x4 = (const float4*)x;
    const float4* __restrict__ m4 = (const float4*)m;
    float4* __restrict__ f4 = (float4*)(out + OFF_FEAT);

    float acc[CC];
#pragma unroll
    for (int c = 0; c < CC; c++) acc[c] = 0.f;
    float ss = 0.f;

    // stage W chunk 0 into buffer 0 (linear: k -> class k>>7, col k&127)
#pragma unroll
    for (int t = 0; t < WPT; t++) {
        int k = tid + t*TPB1;
        sW[0][k] = W[(k >> 7) * FF + (k & 127)];
    }
    __syncthreads();

    for (int ch = 0; ch < NCH; ch++) {
        const int buf = ch & 1;

        // prefetch next W chunk into registers (L2-resident)
        float wpre[WPT];
        if (ch + 1 < NCH) {
#pragma unroll
            for (int t = 0; t < WPT; t++) {
                int k = tid + t*TPB1;
                wpre[t] = W[(k >> 7) * FF + (ch+1)*CF + (k & 127)];
            }
        }

        // front-batch all x/m loads for this chunk (8 LDG.128)
        const int base = row * (FF/4) + ch * (CF/4) + j;
        float4 xv[4], mv[4];
#pragma unroll
        for (int i = 0; i < 4; i++) xv[i] = x4[base + i*8];
#pragma unroll
        for (int i = 0; i < 4; i++) mv[i] = m4[base + i*8];

        // features copy + sum-of-squares + apply mask
#pragma unroll
        for (int i = 0; i < 4; i++) {
            float4 v = xv[i];
            f4[base + i*8] = v;
            ss += v.x*v.x + v.y*v.y + v.z*v.z + v.w*v.w;
            float4 mm = mv[i];
            xv[i] = make_float4(v.x*mm.x, v.y*mm.y, v.z*mm.z, v.w*mm.w);
        }

        // FFMA over classes (smem broadcast reads, 8-lane groups)
        const float4* sW4 = (const float4*)sW[buf];
#pragma unroll
        for (int c = 0; c < CC; c++) {
            float a = acc[c];
#pragma unroll
            for (int i = 0; i < 4; i++) {
                float4 wv = sW4[c * (CF/4) + i*8 + j];
                a += xv[i].x*wv.x + xv[i].y*wv.y + xv[i].z*wv.z + xv[i].w*wv.w;
            }
            acc[c] = a;
        }

        // commit W prefetch into the other buffer
        if (ch + 1 < NCH) {
#pragma unroll
            for (int t = 0; t < WPT; t++) sW[buf ^ 1][tid + t*TPB1] = wpre[t];
        }
        __syncthreads();
    }

    // reduce 8 f-lanes per row, epilogue
#pragma unroll
    for (int c = 0; c < CC; c++) {
        float a = acc[c];
        a += __shfl_down_sync(0xffffffffu, a, 4, 8);
        a += __shfl_down_sync(0xffffffffu, a, 2, 8);
        a += __shfl_down_sync(0xffffffffu, a, 1, 8);
        acc[c] = a;
    }
    ss += __shfl_down_sync(0xffffffffu, ss, 4, 8);
    ss += __shfl_down_sync(0xffffffffu, ss, 2, 8);
    ss += __shfl_down_sync(0xffffffffu, ss, 1, 8);

    if (j == 0) {
        g_mag[row] = sqrtf(ss);
        float mx = acc[0];
#pragma unroll
        for (int c = 1; c < CC; c++) mx = fmaxf(mx, acc[c]);
        float e[CC]; float tot = 0.f;
#pragma unroll
        for (int c = 0; c < CC; c++) { e[c] = __expf(acc[c] - mx); tot += e[c]; }
        float inv = 1.f / tot;
#pragma unroll
        for (int c = 0; c < CC; c++) {
            g_cas[row*CC + c] = acc[c];
            out[OFF_CSM + row*CC + c] = e[c] * inv;
        }
    }
}

// ============================================================
// K2 (merged): blocks 0..15   -> per-batch magmax, stable top-k
//              (jax.lax.top_k semantics), score_bkg.
//              blocks 16..335 -> per-(b,c) mean of top-93 cas.
// ============================================================
constexpr int TPB2 = 768;

__global__ __launch_bounds__(TPB2) void k2_mid(
    const float* __restrict__ sel, float* __restrict__ out)
{
    const int tid = threadIdx.x;

    if (blockIdx.x < BB) {
        // ---------- top-k on magnitudes + score_bkg ----------
        __shared__ float s_mag[TT], s_md[TT], s_rd[TT];
        __shared__ float s_red[TPB2/32];
        __shared__ float s_sum[CC];
        const int b = blockIdx.x;

        for (int t = tid; t < TT; t += TPB2) s_mag[t] = g_mag[b*TT + t];
        __syncthreads();

        float mx = -1.f;
        for (int t = tid; t < TT; t += TPB2) mx = fmaxf(mx, s_mag[t]);
#pragma unroll
        for (int o = 16; o > 0; o >>= 1)
            mx = fmaxf(mx, __shfl_down_sync(0xffffffffu, mx, o));
        if ((tid & 31) == 0) s_red[tid >> 5] = mx;
        __syncthreads();
        if (tid == 0) {
            float mm = s_red[0];
            for (int w = 1; w < TPB2/32; w++) mm = fmaxf(mm, s_red[w]);
            s_red[0] = mm;
        }
        __syncthreads();
        const float magmax = s_red[0];

        for (int t = tid; t < TT; t += TPB2) {
            float sl = sel[b*TT + t];
            s_md[t] = s_mag[t] * sl;
            s_rd[t] = (magmax - s_mag[t]) * sl;
        }
        __syncthreads();

        for (int t = tid; t < TT; t += TPB2) {
            float v = s_md[t]; int rank = 0;
            for (int u = 0; u < TT; u++) {
                float w = s_md[u];
                rank += (w > v) || (w == v && u < t);
            }
            if (rank < KTOP) g_idx_act[b*KTOP + rank] = t;

            float v2 = s_rd[t]; int rank2 = 0;
            for (int u = 0; u < TT; u++) {
                float w = s_rd[u];
                rank2 += (w > v2) || (w == v2 && u < t);
            }
            if (rank2 < KTOP) g_idx_bkg[b*KTOP + rank2] = t;
        }
        __syncthreads();

        if (tid < CC) {
            float s = 0.f;
            for (int i = 0; i < KTOP; i++) {
                int t = g_idx_bkg[b*KTOP + i];
                s += g_cas[(b*TT + t)*CC + tid];
            }
            s_sum[tid] = s * (1.f / KTOP);
        }
        __syncthreads();
        if (tid < CC) {
            float mxv = s_sum[0];
            for (int c = 1; c < CC; c++) mxv = fmaxf(mxv, s_sum[c]);
            float tot = 0.f;
            for (int c = 0; c < CC; c++) tot += __expf(s_sum[c] - mxv);
            out[OFF_SBKG + b*CC + tid] = __expf(s_sum[tid] - mxv) / tot;
        }
    } else {
        // ---------- mean of top-93 of cas[b,:,c] ----------
        __shared__ float s_v[TT];
        __shared__ float s_part[TPB2];
        const int bc = blockIdx.x - BB;
        const int b = bc / CC, c = bc % CC;

        for (int t = tid; t < TT; t += TPB2) s_v[t] = g_cas[(b*TT + t)*CC + c];
        __syncthreads();

        float local = 0.f;
        for (int t = tid; t < TT; t += TPB2) {
            float v = s_v[t]; int rank = 0;
            for (int u = 0; u < TT; u++) {
                float w = s_v[u];
                rank += (w > v) || (w == v && u < t);
            }
            if (rank < KTOP) local += v;
        }
        s_part[tid] = local;
        __syncthreads();
        // 768 = 3*256: three-way fold first, then power-of-2 tree.
        if (tid < 256) s_part[tid] += s_part[tid + 256] + s_part[tid + 512];
        __syncthreads();
        for (int s = 128; s > 0; s >>= 1) {
            if (tid < s) s_part[tid] += s_part[tid + s];
            __syncthreads();
        }
        if (tid == 0) g_actmean[b*CC + c] = s_part[0] * (1.f / KTOP);
    }
}

// ============================================================
// K3: gather feat_act / feat_bkg rows; extra block does the
// score_act softmax (reads g_actmean).
// ============================================================
__global__ __launch_bounds__(256) void k3_gather(
    const float* __restrict__ x, float* __restrict__ out)
{
    const int blk = blockIdx.x;
    if (blk == 2*BB*KTOP) {                     // score_act softmax
#pragma unroll
        for (int i = threadIdx.x; i < BB*CC; i += 256) {
            int b = i / CC, c = i % CC;
            float mxv = g_actmean[b*CC];
            for (int k = 1; k < CC; k++) mxv = fmaxf(mxv, g_actmean[b*CC + k]);
            float s = 0.f;
            for (int k = 0; k < CC; k++) s += __expf(g_actmean[b*CC + k] - mxv);
            out[OFF_SACT + i] = __expf(g_actmean[b*CC + c] - mxv) / s;
        }
        return;
    }
    const int which = blk / (BB*KTOP);          // 0=act, 1=bkg
    const int rem = blk % (BB*KTOP);
    const int b = rem / KTOP, i = rem % KTOP;
    const int t = which ? g_idx_bkg[b*KTOP + i] : g_idx_act[b*KTOP + i];
    const float4* __restrict__ src = (const float4*)(x + (size_t)(b*TT + t) * FF);
    float4* __restrict__ dst =
        (float4*)(out + (which ? OFF_FBKG : OFF_FACT) + (size_t)rem * FF);
#pragma unroll 4
    for (int k = threadIdx.x; k < FF/4; k += 256) dst[k] = src[k];
}

// ============================================================
extern "C" void kernel_launch(void* const* d_in, const int* in_sizes, int n_in,
                              void* d_out, int out_size)
{
    const float *x = nullptr, *W = nullptr, *m = nullptr, *sel = nullptr;
    for (int i = 0; i < n_in; i++) {
        if (in_sizes[i] == CC*FF)            W   = (const float*)d_in[i];
        else if (in_sizes[i] == BB*TT)       sel = (const float*)d_in[i];
        else if (in_sizes[i] == BB*TT*FF) {
            if (!x) x = (const float*)d_in[i];
            else    m = (const float*)d_in[i];
        }
    }
    float* out = (float*)d_out;

    k1_main<<<ROWS/TM, TPB1>>>(x, W, m, out);
    k2_mid<<<BB + BB*CC, TPB2>>>(sel, out);
    k3_gather<<<2*BB*KTOP + 1, 256>>>(x, out);
}